// round 9
// baseline (speedup 1.0000x reference)
#include <cuda_runtime.h>
#include <cstdint>

typedef unsigned long long u64;

#define B_    256
#define T_    512
#define NPAIR 128

// ---- device scratch (no allocations allowed) ------------------------------
__device__ __align__(16) float  g_seqA[(size_t)T_ * B_ * 64];   // 33.5 MB [t][b][64]
__device__ __align__(16) float4 g_pb0[(size_t)T_ * B_];         // 2 MB    [t*256+b]

// ---- packed f32x2 helpers -------------------------------------------------
__device__ __forceinline__ u64 pk2(float a, float b) {
    u64 r; asm("mov.b64 %0, {%1, %2};" : "=l"(r) : "f"(a), "f"(b)); return r;
}
__device__ __forceinline__ void unpk(u64 v, float& a, float& b) {
    asm("mov.b64 {%0, %1}, %2;" : "=f"(a), "=f"(b) : "l"(v));
}
__device__ __forceinline__ u64 ffma2(u64 a, u64 b, u64 c) {
    u64 d; asm("fma.rn.f32x2 %0, %1, %2, %3;" : "=l"(d) : "l"(a), "l"(b), "l"(c)); return d;
}

// ---- fast activations (MUFU ex2+rcp, ~1e-7 err) ---------------------------
#define L2E 1.4426950408889634f
__device__ __forceinline__ float ex2a(float x) {
    float r; asm("ex2.approx.ftz.f32 %0, %1;" : "=f"(r) : "f"(x)); return r;
}
__device__ __forceinline__ float rcpa(float x) {
    float r; asm("rcp.approx.ftz.f32 %0, %1;" : "=f"(r) : "f"(x)); return r;
}
__device__ __forceinline__ float sga(float x) { return rcpa(1.f + ex2a(-L2E * x)); }
__device__ __forceinline__ float tna(float x) {
    return fmaf(-2.f, rcpa(1.f + ex2a(2.f * L2E * x)), 1.f);
}

// ---- fused a0+a1+a2 pipeline: quad-gate lanes, ONE barrier/step ------------
// 128 blocks (one batch pair), 256 threads.
// Lane mapping: warp w, lane l -> unit u = w*8 + (l>>2), gate type gt = l&3
//   (gt: 0=i, 1=f, 2=g, 3=o), gate index gq = gt*64 + u.
// Cell update in-warp: shfl_xor(2) pairs i<->g, f<->o; shfl_xor(1) sends
//   P = sigma(i)*tanh(g) to the f-lane (gt1), which owns c and writes h.
// Step s: a0 gates @t=s, a1 @t=s-1, a2 @t=s-2.
// Weights: whh_a0(wr0), wih_a1(wr1), whh_a1(wr2) dim-packed in regs;
//   wih_a2(wT2), whh_a2(wT3) in smem transposed [chunk16B][gate].
//
// dynamic smem layout (bytes):
//   [0,      65536)   wT2 = wih_a2  as ulonglong2[16][256]
//   [65536, 131072)   wT3 = whh_a2
//   [131072,135168)   xs  = float[2][512]
//   [135168,138240)   hs  = float[2 phase][3 layer][2 batch][64]
#define SMEM_FUSE_BYTES 138240

__global__ __launch_bounds__(256, 1) void fuseA(
    const float* __restrict__ x,
    const float* __restrict__ wih_a0, const float* __restrict__ whh_a0,
    const float* __restrict__ bih_a0, const float* __restrict__ bhh_a0,
    const float* __restrict__ wih_a1, const float* __restrict__ whh_a1,
    const float* __restrict__ bih_a1, const float* __restrict__ bhh_a1,
    const float* __restrict__ wih_a2, const float* __restrict__ whh_a2,
    const float* __restrict__ bih_a2, const float* __restrict__ bhh_a2)
{
    extern __shared__ __align__(16) char smem[];
    ulonglong2* wT2 = reinterpret_cast<ulonglong2*>(smem);
    ulonglong2* wT3 = reinterpret_cast<ulonglong2*>(smem + 65536);
    float*  xs  = reinterpret_cast<float*>(smem + 131072);   // [2][512]
    float*  hs  = reinterpret_cast<float*>(smem + 135168);   // [2][3][2][64]

    const int tid  = threadIdx.x;
    const int lane = tid & 31, w = tid >> 5;
    const int gt   = lane & 3;                 // 0=i 1=f 2=g 3=o
    const int u    = w * 8 + (lane >> 2);      // unit 0..63
    const int gq   = gt * 64 + u;              // gate row index
    const bool isF = (gt == 1);
    const int pair = blockIdx.x;

    // ---- register weight sets (dim-packed u64 rows: 32 u64 each) ----
    u64 wr0[32], wr1[32], wr2[32];
    {
        const u64* p0 = reinterpret_cast<const u64*>(whh_a0) + (size_t)gq * 32;
        const u64* p1 = reinterpret_cast<const u64*>(wih_a1) + (size_t)gq * 32;
        const u64* p2 = reinterpret_cast<const u64*>(whh_a1) + (size_t)gq * 32;
#pragma unroll
        for (int j = 0; j < 32; ++j) {
            wr0[j] = __ldg(p0 + j);
            wr1[j] = __ldg(p1 + j);
            wr2[j] = __ldg(p2 + j);
        }
    }
    // ---- smem transposed weight sets: wT[i][g] = 16B chunk i of row g ----
    {
        const ulonglong2* p2 = reinterpret_cast<const ulonglong2*>(wih_a2) + (size_t)tid * 16;
        const ulonglong2* p3 = reinterpret_cast<const ulonglong2*>(whh_a2) + (size_t)tid * 16;
#pragma unroll
        for (int i = 0; i < 16; ++i) {
            wT2[i * 256 + tid] = __ldg(p2 + i);
            wT3[i * 256 + tid] = __ldg(p3 + i);
        }
    }
    // ---- x staging ----
#pragma unroll
    for (int k = 0; k < 4; ++k) {
        int i = tid + 256 * k, bl = i >> 9, t = i & 511;
        xs[bl * 512 + t] = x[(size_t)(pair * 2 + bl) * T_ + t];
    }
    // ---- h init: both phases to zero ----
    if (tid < 128) {
#pragma unroll
        for (int q = 0; q < 6; ++q) hs[q * 128 + tid] = 0.f;
    }

    const float bias0 = __ldg(bih_a0 + gq) + __ldg(bhh_a0 + gq);
    const float bias1 = __ldg(bih_a1 + gq) + __ldg(bhh_a1 + gq);
    const float bias2 = __ldg(bih_a2 + gq) + __ldg(bhh_a2 + gq);
    const float wx0   = __ldg(wih_a0 + gq);

    const bool istanh = (gt == 2);
    const float ca = istanh ? 2.f * L2E : -L2E;
    const float aa = istanh ? 1.f : 0.f;
    const float bm = istanh ? -2.f : 1.f;

    float c0a = 0.f, c0b = 0.f, c1a = 0.f, c1b = 0.f, c2a = 0.f, c2b = 0.f;
    int p = 0;
    __syncthreads();

#pragma unroll 1
    for (int s = 0; s < T_ + 2; ++s) {
        const bool L0 = (s < T_);
        const bool L1 = (s >= 1) & (s < T_ + 1);
        const bool L2 = (s >= 2);
        const float* hb = hs + p * 384;
        float* hw = hs + (p ^ 1) * 384;

        float v0a = 0.f, v0b = 0.f, p1a = 0.f, p1b = 0.f;
        float h1a = 0.f, h1b = 0.f, p2a = 0.f, p2b = 0.f;
        float h2a = 0.f, h2b = 0.f;

        // ---- group A: whh_a0 (wr0) + wih_a1 (wr1) over h0 -- all regs ----
        if (L0 | L1) {
            const ulonglong2* q0p = reinterpret_cast<const ulonglong2*>(hb + 0);
            const ulonglong2* q1p = reinterpret_cast<const ulonglong2*>(hb + 64);
            u64 ax = 0, bx = 0, ix = 0, jx = 0;
#pragma unroll
            for (int i = 0; i < 16; ++i) {
                ulonglong2 q0 = q0p[i], q1 = q1p[i];
                ax = ffma2(wr0[2 * i], q0.x, ax); ax = ffma2(wr0[2 * i + 1], q0.y, ax);
                bx = ffma2(wr0[2 * i], q1.x, bx); bx = ffma2(wr0[2 * i + 1], q1.y, bx);
                ix = ffma2(wr1[2 * i], q0.x, ix); ix = ffma2(wr1[2 * i + 1], q0.y, ix);
                jx = ffma2(wr1[2 * i], q1.x, jx); jx = ffma2(wr1[2 * i + 1], q1.y, jx);
            }
            float e, o;
            unpk(ax, e, o); v0a = e + o;
            unpk(bx, e, o); v0b = e + o;
            unpk(ix, e, o); p1a = e + o;
            unpk(jx, e, o); p1b = e + o;
        }
        // ---- group B: whh_a1 (wr2 regs) + wih_a2 (wT2 smem) over h1 ----
        if (L1 | L2) {
            const ulonglong2* q0p = reinterpret_cast<const ulonglong2*>(hb + 128);
            const ulonglong2* q1p = reinterpret_cast<const ulonglong2*>(hb + 192);
            u64 ax = 0, bx = 0, ix = 0, jx = 0;
#pragma unroll
            for (int i = 0; i < 16; ++i) {
                ulonglong2 q0 = q0p[i], q1 = q1p[i];
                ulonglong2 wv = wT2[i * 256 + gq];
                ax = ffma2(wr2[2 * i], q0.x, ax); ax = ffma2(wr2[2 * i + 1], q0.y, ax);
                bx = ffma2(wr2[2 * i], q1.x, bx); bx = ffma2(wr2[2 * i + 1], q1.y, bx);
                ix = ffma2(wv.x, q0.x, ix);       ix = ffma2(wv.y, q0.y, ix);
                jx = ffma2(wv.x, q1.x, jx);       jx = ffma2(wv.y, q1.y, jx);
            }
            float e, o;
            unpk(ax, e, o); h1a = e + o;
            unpk(bx, e, o); h1b = e + o;
            unpk(ix, e, o); p2a = e + o;
            unpk(jx, e, o); p2b = e + o;
        }
        // ---- group C: whh_a2 (wT3 smem) over h2 ----
        if (L2) {
            const ulonglong2* q0p = reinterpret_cast<const ulonglong2*>(hb + 256);
            const ulonglong2* q1p = reinterpret_cast<const ulonglong2*>(hb + 320);
            u64 ax = 0, bx = 0;
#pragma unroll
            for (int i = 0; i < 16; ++i) {
                ulonglong2 q0 = q0p[i], q1 = q1p[i];
                ulonglong2 wv = wT3[i * 256 + gq];
                ax = ffma2(wv.x, q0.x, ax); ax = ffma2(wv.y, q0.y, ax);
                bx = ffma2(wv.x, q1.x, bx); bx = ffma2(wv.y, q1.y, bx);
            }
            float e, o;
            unpk(ax, e, o); h2a = e + o;
            unpk(bx, e, o); h2b = e + o;
        }

        // ---- per-layer in-warp cell updates (2 shfl per batch-layer) ----
        if (L0) {
            float va = v0a + fmaf(wx0, xs[s], bias0);
            float vb = v0b + fmaf(wx0, xs[512 + s], bias0);
            float ra = fmaf(bm, rcpa(1.f + ex2a(ca * va)), aa);
            float rb = fmaf(bm, rcpa(1.f + ex2a(ca * vb)), aa);
            float r2a = __shfl_xor_sync(0xffffffffu, ra, 2);
            float r2b = __shfl_xor_sync(0xffffffffu, rb, 2);
            float r1a = __shfl_xor_sync(0xffffffffu, ra * r2a, 1);
            float r1b = __shfl_xor_sync(0xffffffffu, rb * r2b, 1);
            if (isF) {
                c0a = fmaf(ra, c0a, r1a);           // ra=sig(f), r1=sig(i)*tanh(g)
                c0b = fmaf(rb, c0b, r1b);
                hw[u]      = r2a * tna(c0a);        // r2=sig(o)
                hw[64 + u] = r2b * tna(c0b);
            }
        }
        if (L1) {
            float va = h1a + p1a + bias1;
            float vb = h1b + p1b + bias1;
            float ra = fmaf(bm, rcpa(1.f + ex2a(ca * va)), aa);
            float rb = fmaf(bm, rcpa(1.f + ex2a(ca * vb)), aa);
            float r2a = __shfl_xor_sync(0xffffffffu, ra, 2);
            float r2b = __shfl_xor_sync(0xffffffffu, rb, 2);
            float r1a = __shfl_xor_sync(0xffffffffu, ra * r2a, 1);
            float r1b = __shfl_xor_sync(0xffffffffu, rb * r2b, 1);
            if (isF) {
                c1a = fmaf(ra, c1a, r1a);
                c1b = fmaf(rb, c1b, r1b);
                hw[128 + u] = r2a * tna(c1a);
                hw[192 + u] = r2b * tna(c1b);
            }
        }
        if (L2) {
            float va = h2a + p2a + bias2;
            float vb = h2b + p2b + bias2;
            float ra = fmaf(bm, rcpa(1.f + ex2a(ca * va)), aa);
            float rb = fmaf(bm, rcpa(1.f + ex2a(ca * vb)), aa);
            float r2a = __shfl_xor_sync(0xffffffffu, ra, 2);
            float r2b = __shfl_xor_sync(0xffffffffu, rb, 2);
            float r1a = __shfl_xor_sync(0xffffffffu, ra * r2a, 1);
            float r1b = __shfl_xor_sync(0xffffffffu, rb * r2b, 1);
            if (isF) {
                c2a = fmaf(ra, c2a, r1a);
                c2b = fmaf(rb, c2b, r1b);
                float ha = r2a * tna(c2a);
                float hb2 = r2b * tna(c2b);
                hw[256 + u] = ha;
                hw[320 + u] = hb2;
                g_seqA[((size_t)(s - 2) * B_ + pair * 2 + 0) * 64 + u] = ha;
                g_seqA[((size_t)(s - 2) * B_ + pair * 2 + 1) * 64 + u] = hb2;
            }
        }
        __syncthreads();
        p ^= 1;
    }
}

// ---------------------------------------------------------------------------
// b0 pre-gates: g_pb0[t*256+b] = bias_b0 + W_ih_b0[4,64] . seqA[t][b]
// ---------------------------------------------------------------------------
__global__ __launch_bounds__(256, 1) void preb0(
    const float* __restrict__ w_ih, const float* __restrict__ b_ih,
    const float* __restrict__ b_hh)
{
    __shared__ u64 wsm[128];
    __shared__ float bsm[4];
    const int tid = threadIdx.x;
    if (tid < 128) wsm[tid] = __ldg(reinterpret_cast<const u64*>(w_ih) + tid);
    if (tid < 4) bsm[tid] = __ldg(b_ih + tid) + __ldg(b_hh + tid);
    __syncthreads();

    const size_t slot = (size_t)blockIdx.x * 256 + tid;  // = t*256 + b
    const u64* xp = reinterpret_cast<const u64*>(g_seqA) + slot * 32;
    u64 acc[4] = {0ull, 0ull, 0ull, 0ull};
#pragma unroll 8
    for (int j = 0; j < 32; ++j) {
        u64 xv = __ldg(xp + j);
#pragma unroll
        for (int gg = 0; gg < 4; ++gg)
            acc[gg] = ffma2(wsm[gg * 32 + j], xv, acc[gg]);
    }
    float r[4];
#pragma unroll
    for (int gg = 0; gg < 4; ++gg) {
        float e, o; unpk(acc[gg], e, o);
        r[gg] = e + o + bsm[gg];
    }
    g_pb0[slot] = make_float4(r[0], r[1], r[2], r[3]);
}

// ---------------------------------------------------------------------------
// b0,b1,b2 scalar recurrences, layer-pipelined. 8 blocks x 32 threads.
// ---------------------------------------------------------------------------
__device__ __forceinline__ void step1(float4 pre, float4 whh, float& c, float& h) {
    float iv = sga(fmaf(whh.x, h, pre.x));
    float fv = sga(fmaf(whh.y, h, pre.y));
    float gv = tna(fmaf(whh.z, h, pre.z));
    float ov = sga(fmaf(whh.w, h, pre.w));
    c = fmaf(fv, c, iv * gv);
    h = ov * tna(c);
}

__global__ __launch_bounds__(32, 1) void b012(
    const float* __restrict__ whh0,
    const float* __restrict__ wih1, const float* __restrict__ whh1,
    const float* __restrict__ bih1, const float* __restrict__ bhh1,
    const float* __restrict__ wih2, const float* __restrict__ whh2,
    const float* __restrict__ bih2, const float* __restrict__ bhh2,
    float* __restrict__ out)
{
    const int b = blockIdx.x * 32 + threadIdx.x;
    float4 W0 = make_float4(whh0[0], whh0[1], whh0[2], whh0[3]);
    float4 I1 = make_float4(wih1[0], wih1[1], wih1[2], wih1[3]);
    float4 H1 = make_float4(whh1[0], whh1[1], whh1[2], whh1[3]);
    float4 B1 = make_float4(bih1[0] + bhh1[0], bih1[1] + bhh1[1],
                            bih1[2] + bhh1[2], bih1[3] + bhh1[3]);
    float4 I2 = make_float4(wih2[0], wih2[1], wih2[2], wih2[3]);
    float4 H2 = make_float4(whh2[0], whh2[1], whh2[2], whh2[3]);
    float4 B2 = make_float4(bih2[0] + bhh2[0], bih2[1] + bhh2[1],
                            bih2[2] + bhh2[2], bih2[3] + bhh2[3]);

    float c0 = 0.f, h0 = 0.f, c1 = 0.f, h1 = 0.f, c2 = 0.f, h2v = 0.f;
    float4 p0 = g_pb0[b];
    float4 p1 = g_pb0[256 + b];

    for (int tt = 0; tt < T_ + 2; ++tt) {
        float4 pn = (tt + 2 < T_) ? g_pb0[(size_t)(tt + 2) * 256 + b]
                                  : make_float4(0.f, 0.f, 0.f, 0.f);
        float in0 = h0, in1 = h1;
        if (tt < T_) step1(p0, W0, c0, h0);
        if (tt >= 1 && tt < T_ + 1) {
            float4 pre = make_float4(fmaf(I1.x, in0, B1.x), fmaf(I1.y, in0, B1.y),
                                     fmaf(I1.z, in0, B1.z), fmaf(I1.w, in0, B1.w));
            step1(pre, H1, c1, h1);
        }
        if (tt >= 2) {
            float4 pre = make_float4(fmaf(I2.x, in1, B2.x), fmaf(I2.y, in1, B2.y),
                                     fmaf(I2.z, in1, B2.z), fmaf(I2.w, in1, B2.w));
            step1(pre, H2, c2, h2v);
            out[(size_t)b * T_ + (tt - 2)] = h2v;
        }
        p0 = p1; p1 = pn;
    }
}

// ---------------------------------------------------------------------------
extern "C" void kernel_launch(void* const* d_in, const int* in_sizes, int n_in,
                              void* d_out, int out_size)
{
    const float* x = (const float*)d_in[0];
    const float *wih_a0 = (const float*)d_in[1],  *whh_a0 = (const float*)d_in[2];
    const float *bih_a0 = (const float*)d_in[3],  *bhh_a0 = (const float*)d_in[4];
    const float *wih_a1 = (const float*)d_in[5],  *whh_a1 = (const float*)d_in[6];
    const float *bih_a1 = (const float*)d_in[7],  *bhh_a1 = (const float*)d_in[8];
    const float *wih_a2 = (const float*)d_in[9],  *whh_a2 = (const float*)d_in[10];
    const float *bih_a2 = (const float*)d_in[11], *bhh_a2 = (const float*)d_in[12];
    const float *wih_b0 = (const float*)d_in[13], *whh_b0 = (const float*)d_in[14];
    const float *bih_b0 = (const float*)d_in[15], *bhh_b0 = (const float*)d_in[16];
    const float *wih_b1 = (const float*)d_in[17], *whh_b1 = (const float*)d_in[18];
    const float *bih_b1 = (const float*)d_in[19], *bhh_b1 = (const float*)d_in[20];
    const float *wih_b2 = (const float*)d_in[21], *whh_b2 = (const float*)d_in[22];
    const float *bih_b2 = (const float*)d_in[23], *bhh_b2 = (const float*)d_in[24];
    float* out = (float*)d_out;

    cudaFuncSetAttribute(fuseA, cudaFuncAttributeMaxDynamicSharedMemorySize,
                         SMEM_FUSE_BYTES);

    // fused a0+a1+a2 pipeline -> g_seqA
    fuseA<<<NPAIR, 256, SMEM_FUSE_BYTES>>>(
        x,
        wih_a0, whh_a0, bih_a0, bhh_a0,
        wih_a1, whh_a1, bih_a1, bhh_a1,
        wih_a2, whh_a2, bih_a2, bhh_a2);
    // b0 pre-gates from g_seqA
    preb0<<<512, 256>>>(wih_b0, bih_b0, bhh_b0);
    // b0/b1/b2 fused scalar recurrences -> out
    b012<<<8, 32>>>(whh_b0, wih_b1, whh_b1, bih_b1, bhh_b1,
                    wih_b2, whh_b2, bih_b2, bhh_b2, out);
}

// round 10
// speedup vs baseline: 1.6821x; 1.6821x over previous
#include <cuda_runtime.h>
#include <cstdint>

typedef unsigned long long u64;

#define B_    256
#define T_    512
#define NPAIR 128

// ---- device scratch (no allocations allowed) ------------------------------
__device__ __align__(16) float  g_seqA[(size_t)T_ * B_ * 64];   // 33.5 MB [t][b][64]
__device__ __align__(16) float4 g_pb0[(size_t)T_ * B_];         // 2 MB    [t*256+b]

// ---- packed f32x2 helpers -------------------------------------------------
__device__ __forceinline__ u64 pk2(float a, float b) {
    u64 r; asm("mov.b64 %0, {%1, %2};" : "=l"(r) : "f"(a), "f"(b)); return r;
}
__device__ __forceinline__ void unpk(u64 v, float& a, float& b) {
    asm("mov.b64 {%0, %1}, %2;" : "=f"(a), "=f"(b) : "l"(v));
}
__device__ __forceinline__ u64 ffma2(u64 a, u64 b, u64 c) {
    u64 d; asm("fma.rn.f32x2 %0, %1, %2, %3;" : "=l"(d) : "l"(a), "l"(b), "l"(c)); return d;
}

// ---- fast activations (MUFU ex2+rcp, ~1e-7 err) ---------------------------
#define L2E 1.4426950408889634f
__device__ __forceinline__ float ex2a(float x) {
    float r; asm("ex2.approx.ftz.f32 %0, %1;" : "=f"(r) : "f"(x)); return r;
}
__device__ __forceinline__ float rcpa(float x) {
    float r; asm("rcp.approx.ftz.f32 %0, %1;" : "=f"(r) : "f"(x)); return r;
}
__device__ __forceinline__ float sga(float x) { return rcpa(1.f + ex2a(-L2E * x)); }
__device__ __forceinline__ float tna(float x) {
    return fmaf(-2.f, rcpa(1.f + ex2a(2.f * L2E * x)), 1.f);
}

// ---- fused a0+a1+a2 pipeline: quad-gate lanes, ONE barrier/step ------------
// 128 blocks (one batch pair), 256 threads.
// Lane mapping: warp w, lane l -> unit u = w*8 + (l>>2), gate type gt = l&3
//   (gt: 0=i, 1=f, 2=g, 3=o), gate index gq = gt*64 + u.
// Cell update in-warp: shfl_xor(2) pairs i<->g, f<->o; shfl_xor(1) sends
//   P = sigma(i)*tanh(g) to the f-lane (gt1), which owns c and writes h.
// Step s: a0 gates @t=s, a1 @t=s-1, a2 @t=s-2.
// Weights: whh_a0(wr0), wih_a1(wr1), whh_a1(wr2) dim-packed in regs;
//   wih_a2(wT2), whh_a2(wT3) in smem, PERMUTED at staging so slot tid holds
//   row gq(tid) -> all main-loop reads are wT[i*256+tid] (coalesced,
//   conflict-free; fixes the R9 4-way bank conflict).
//
// dynamic smem layout (bytes):
//   [0,      65536)   wT2 = wih_a2  as ulonglong2[16][256] (permuted rows)
//   [65536, 131072)   wT3 = whh_a2  (permuted rows)
//   [131072,135168)   xs  = float[2][512]
//   [135168,138240)   hs  = float[2 phase][3 layer][2 batch][64]
#define SMEM_FUSE_BYTES 138240

__global__ __launch_bounds__(256, 1) void fuseA(
    const float* __restrict__ x,
    const float* __restrict__ wih_a0, const float* __restrict__ whh_a0,
    const float* __restrict__ bih_a0, const float* __restrict__ bhh_a0,
    const float* __restrict__ wih_a1, const float* __restrict__ whh_a1,
    const float* __restrict__ bih_a1, const float* __restrict__ bhh_a1,
    const float* __restrict__ wih_a2, const float* __restrict__ whh_a2,
    const float* __restrict__ bih_a2, const float* __restrict__ bhh_a2)
{
    extern __shared__ __align__(16) char smem[];
    ulonglong2* wT2 = reinterpret_cast<ulonglong2*>(smem);
    ulonglong2* wT3 = reinterpret_cast<ulonglong2*>(smem + 65536);
    float*  xs  = reinterpret_cast<float*>(smem + 131072);   // [2][512]
    float*  hs  = reinterpret_cast<float*>(smem + 135168);   // [2][3][2][64]

    const int tid  = threadIdx.x;
    const int lane = tid & 31, w = tid >> 5;
    const int gt   = lane & 3;                 // 0=i 1=f 2=g 3=o
    const int u    = w * 8 + (lane >> 2);      // unit 0..63
    const int gq   = gt * 64 + u;              // gate row index
    const bool isF = (gt == 1);
    const int pair = blockIdx.x;

    // ---- register weight sets (dim-packed u64 rows: 32 u64 each) ----
    u64 wr0[32], wr1[32], wr2[32];
    {
        const u64* p0 = reinterpret_cast<const u64*>(whh_a0) + (size_t)gq * 32;
        const u64* p1 = reinterpret_cast<const u64*>(wih_a1) + (size_t)gq * 32;
        const u64* p2 = reinterpret_cast<const u64*>(whh_a1) + (size_t)gq * 32;
#pragma unroll
        for (int j = 0; j < 32; ++j) {
            wr0[j] = __ldg(p0 + j);
            wr1[j] = __ldg(p1 + j);
            wr2[j] = __ldg(p2 + j);
        }
    }
    // ---- smem weight sets, PERMUTED: slot tid holds chunks of row gq ----
    {
        const ulonglong2* p2 = reinterpret_cast<const ulonglong2*>(wih_a2) + (size_t)gq * 16;
        const ulonglong2* p3 = reinterpret_cast<const ulonglong2*>(whh_a2) + (size_t)gq * 16;
#pragma unroll 4
        for (int i = 0; i < 16; ++i) {
            wT2[i * 256 + tid] = __ldg(p2 + i);
            wT3[i * 256 + tid] = __ldg(p3 + i);
        }
    }
    // ---- x staging ----
#pragma unroll 2
    for (int k = 0; k < 4; ++k) {
        int i = tid + 256 * k, bl = i >> 9, t = i & 511;
        xs[bl * 512 + t] = x[(size_t)(pair * 2 + bl) * T_ + t];
    }
    // ---- h init: both phases to zero ----
    if (tid < 128) {
#pragma unroll 2
        for (int q = 0; q < 6; ++q) hs[q * 128 + tid] = 0.f;
    }

    const float bias0 = __ldg(bih_a0 + gq) + __ldg(bhh_a0 + gq);
    const float bias1 = __ldg(bih_a1 + gq) + __ldg(bhh_a1 + gq);
    const float bias2 = __ldg(bih_a2 + gq) + __ldg(bhh_a2 + gq);
    const float wx0   = __ldg(wih_a0 + gq);

    const bool istanh = (gt == 2);
    const float ca = istanh ? 2.f * L2E : -L2E;
    const float aa = istanh ? 1.f : 0.f;
    const float bm = istanh ? -2.f : 1.f;

    float c0a = 0.f, c0b = 0.f, c1a = 0.f, c1b = 0.f, c2a = 0.f, c2b = 0.f;
    int p = 0;
    __syncthreads();

#pragma unroll 1
    for (int s = 0; s < T_ + 2; ++s) {
        const bool L0 = (s < T_);
        const bool L1 = (s >= 1) & (s < T_ + 1);
        const bool L2 = (s >= 2);
        const float* hb = hs + p * 384;
        float* hw = hs + (p ^ 1) * 384;

        float v0a = 0.f, v0b = 0.f, p1a = 0.f, p1b = 0.f;
        float h1a = 0.f, h1b = 0.f, p2a = 0.f, p2b = 0.f;
        float h2a = 0.f, h2b = 0.f;

        // ---- group A: whh_a0 (wr0) + wih_a1 (wr1) over h0 -- all regs ----
        if (L0 | L1) {
            const ulonglong2* q0p = reinterpret_cast<const ulonglong2*>(hb + 0);
            const ulonglong2* q1p = reinterpret_cast<const ulonglong2*>(hb + 64);
            u64 ax = 0, bx = 0, ix = 0, jx = 0;
#pragma unroll
            for (int i = 0; i < 16; ++i) {
                ulonglong2 q0 = q0p[i], q1 = q1p[i];
                ax = ffma2(wr0[2 * i], q0.x, ax); ax = ffma2(wr0[2 * i + 1], q0.y, ax);
                bx = ffma2(wr0[2 * i], q1.x, bx); bx = ffma2(wr0[2 * i + 1], q1.y, bx);
                ix = ffma2(wr1[2 * i], q0.x, ix); ix = ffma2(wr1[2 * i + 1], q0.y, ix);
                jx = ffma2(wr1[2 * i], q1.x, jx); jx = ffma2(wr1[2 * i + 1], q1.y, jx);
            }
            float e, o;
            unpk(ax, e, o); v0a = e + o;
            unpk(bx, e, o); v0b = e + o;
            unpk(ix, e, o); p1a = e + o;
            unpk(jx, e, o); p1b = e + o;
        }
        // ---- group B: whh_a1 (wr2 regs) + wih_a2 (wT2 smem) over h1 ----
        if (L1 | L2) {
            const ulonglong2* q0p = reinterpret_cast<const ulonglong2*>(hb + 128);
            const ulonglong2* q1p = reinterpret_cast<const ulonglong2*>(hb + 192);
            u64 ax = 0, bx = 0, ix = 0, jx = 0;
#pragma unroll
            for (int i = 0; i < 16; ++i) {
                ulonglong2 q0 = q0p[i], q1 = q1p[i];
                ulonglong2 wv = wT2[i * 256 + tid];
                ax = ffma2(wr2[2 * i], q0.x, ax); ax = ffma2(wr2[2 * i + 1], q0.y, ax);
                bx = ffma2(wr2[2 * i], q1.x, bx); bx = ffma2(wr2[2 * i + 1], q1.y, bx);
                ix = ffma2(wv.x, q0.x, ix);       ix = ffma2(wv.y, q0.y, ix);
                jx = ffma2(wv.x, q1.x, jx);       jx = ffma2(wv.y, q1.y, jx);
            }
            float e, o;
            unpk(ax, e, o); h1a = e + o;
            unpk(bx, e, o); h1b = e + o;
            unpk(ix, e, o); p2a = e + o;
            unpk(jx, e, o); p2b = e + o;
        }
        // ---- group C: whh_a2 (wT3 smem) over h2 ----
        if (L2) {
            const ulonglong2* q0p = reinterpret_cast<const ulonglong2*>(hb + 256);
            const ulonglong2* q1p = reinterpret_cast<const ulonglong2*>(hb + 320);
            u64 ax = 0, bx = 0;
#pragma unroll
            for (int i = 0; i < 16; ++i) {
                ulonglong2 q0 = q0p[i], q1 = q1p[i];
                ulonglong2 wv = wT3[i * 256 + tid];
                ax = ffma2(wv.x, q0.x, ax); ax = ffma2(wv.y, q0.y, ax);
                bx = ffma2(wv.x, q1.x, bx); bx = ffma2(wv.y, q1.y, bx);
            }
            float e, o;
            unpk(ax, e, o); h2a = e + o;
            unpk(bx, e, o); h2b = e + o;
        }

        // ---- per-layer in-warp cell updates (3 shfl per batch-layer) ----
        if (L0) {
            float va = v0a + fmaf(wx0, xs[s], bias0);
            float vb = v0b + fmaf(wx0, xs[512 + s], bias0);
            float ra = fmaf(bm, rcpa(1.f + ex2a(ca * va)), aa);
            float rb = fmaf(bm, rcpa(1.f + ex2a(ca * vb)), aa);
            float r2a = __shfl_xor_sync(0xffffffffu, ra, 2);
            float r2b = __shfl_xor_sync(0xffffffffu, rb, 2);
            float r1a = __shfl_xor_sync(0xffffffffu, ra * r2a, 1);
            float r1b = __shfl_xor_sync(0xffffffffu, rb * r2b, 1);
            if (isF) {
                c0a = fmaf(ra, c0a, r1a);           // ra=sig(f), r1=sig(i)*tanh(g)
                c0b = fmaf(rb, c0b, r1b);
                hw[u]      = r2a * tna(c0a);        // r2=sig(o)
                hw[64 + u] = r2b * tna(c0b);
            }
        }
        if (L1) {
            float va = h1a + p1a + bias1;
            float vb = h1b + p1b + bias1;
            float ra = fmaf(bm, rcpa(1.f + ex2a(ca * va)), aa);
            float rb = fmaf(bm, rcpa(1.f + ex2a(ca * vb)), aa);
            float r2a = __shfl_xor_sync(0xffffffffu, ra, 2);
            float r2b = __shfl_xor_sync(0xffffffffu, rb, 2);
            float r1a = __shfl_xor_sync(0xffffffffu, ra * r2a, 1);
            float r1b = __shfl_xor_sync(0xffffffffu, rb * r2b, 1);
            if (isF) {
                c1a = fmaf(ra, c1a, r1a);
                c1b = fmaf(rb, c1b, r1b);
                hw[128 + u] = r2a * tna(c1a);
                hw[192 + u] = r2b * tna(c1b);
            }
        }
        if (L2) {
            float va = h2a + p2a + bias2;
            float vb = h2b + p2b + bias2;
            float ra = fmaf(bm, rcpa(1.f + ex2a(ca * va)), aa);
            float rb = fmaf(bm, rcpa(1.f + ex2a(ca * vb)), aa);
            float r2a = __shfl_xor_sync(0xffffffffu, ra, 2);
            float r2b = __shfl_xor_sync(0xffffffffu, rb, 2);
            float r1a = __shfl_xor_sync(0xffffffffu, ra * r2a, 1);
            float r1b = __shfl_xor_sync(0xffffffffu, rb * r2b, 1);
            if (isF) {
                c2a = fmaf(ra, c2a, r1a);
                c2b = fmaf(rb, c2b, r1b);
                float ha = r2a * tna(c2a);
                float hb2 = r2b * tna(c2b);
                hw[256 + u] = ha;
                hw[320 + u] = hb2;
                g_seqA[((size_t)(s - 2) * B_ + pair * 2 + 0) * 64 + u] = ha;
                g_seqA[((size_t)(s - 2) * B_ + pair * 2 + 1) * 64 + u] = hb2;
            }
        }
        __syncthreads();
        p ^= 1;
    }
}

// ---------------------------------------------------------------------------
// b0 pre-gates: g_pb0[t*256+b] = bias_b0 + W_ih_b0[4,64] . seqA[t][b]
// ---------------------------------------------------------------------------
__global__ __launch_bounds__(256, 1) void preb0(
    const float* __restrict__ w_ih, const float* __restrict__ b_ih,
    const float* __restrict__ b_hh)
{
    __shared__ u64 wsm[128];
    __shared__ float bsm[4];
    const int tid = threadIdx.x;
    if (tid < 128) wsm[tid] = __ldg(reinterpret_cast<const u64*>(w_ih) + tid);
    if (tid < 4) bsm[tid] = __ldg(b_ih + tid) + __ldg(b_hh + tid);
    __syncthreads();

    const size_t slot = (size_t)blockIdx.x * 256 + tid;  // = t*256 + b
    const u64* xp = reinterpret_cast<const u64*>(g_seqA) + slot * 32;
    u64 acc[4] = {0ull, 0ull, 0ull, 0ull};
#pragma unroll 8
    for (int j = 0; j < 32; ++j) {
        u64 xv = __ldg(xp + j);
#pragma unroll
        for (int gg = 0; gg < 4; ++gg)
            acc[gg] = ffma2(wsm[gg * 32 + j], xv, acc[gg]);
    }
    float r[4];
#pragma unroll
    for (int gg = 0; gg < 4; ++gg) {
        float e, o; unpk(acc[gg], e, o);
        r[gg] = e + o + bsm[gg];
    }
    g_pb0[slot] = make_float4(r[0], r[1], r[2], r[3]);
}

// ---------------------------------------------------------------------------
// b0,b1,b2 scalar recurrences, layer-pipelined. 8 blocks x 32 threads.
// ---------------------------------------------------------------------------
__device__ __forceinline__ void step1(float4 pre, float4 whh, float& c, float& h) {
    float iv = sga(fmaf(whh.x, h, pre.x));
    float fv = sga(fmaf(whh.y, h, pre.y));
    float gv = tna(fmaf(whh.z, h, pre.z));
    float ov = sga(fmaf(whh.w, h, pre.w));
    c = fmaf(fv, c, iv * gv);
    h = ov * tna(c);
}

__global__ __launch_bounds__(32, 1) void b012(
    const float* __restrict__ whh0,
    const float* __restrict__ wih1, const float* __restrict__ whh1,
    const float* __restrict__ bih1, const float* __restrict__ bhh1,
    const float* __restrict__ wih2, const float* __restrict__ whh2,
    const float* __restrict__ bih2, const float* __restrict__ bhh2,
    float* __restrict__ out)
{
    const int b = blockIdx.x * 32 + threadIdx.x;
    float4 W0 = make_float4(whh0[0], whh0[1], whh0[2], whh0[3]);
    float4 I1 = make_float4(wih1[0], wih1[1], wih1[2], wih1[3]);
    float4 H1 = make_float4(whh1[0], whh1[1], whh1[2], whh1[3]);
    float4 B1 = make_float4(bih1[0] + bhh1[0], bih1[1] + bhh1[1],
                            bih1[2] + bhh1[2], bih1[3] + bhh1[3]);
    float4 I2 = make_float4(wih2[0], wih2[1], wih2[2], wih2[3]);
    float4 H2 = make_float4(whh2[0], whh2[1], whh2[2], whh2[3]);
    float4 B2 = make_float4(bih2[0] + bhh2[0], bih2[1] + bhh2[1],
                            bih2[2] + bhh2[2], bih2[3] + bhh2[3]);

    float c0 = 0.f, h0 = 0.f, c1 = 0.f, h1 = 0.f, c2 = 0.f, h2v = 0.f;
    float4 p0 = g_pb0[b];
    float4 p1 = g_pb0[256 + b];

    for (int tt = 0; tt < T_ + 2; ++tt) {
        float4 pn = (tt + 2 < T_) ? g_pb0[(size_t)(tt + 2) * 256 + b]
                                  : make_float4(0.f, 0.f, 0.f, 0.f);
        float in0 = h0, in1 = h1;
        if (tt < T_) step1(p0, W0, c0, h0);
        if (tt >= 1 && tt < T_ + 1) {
            float4 pre = make_float4(fmaf(I1.x, in0, B1.x), fmaf(I1.y, in0, B1.y),
                                     fmaf(I1.z, in0, B1.z), fmaf(I1.w, in0, B1.w));
            step1(pre, H1, c1, h1);
        }
        if (tt >= 2) {
            float4 pre = make_float4(fmaf(I2.x, in1, B2.x), fmaf(I2.y, in1, B2.y),
                                     fmaf(I2.z, in1, B2.z), fmaf(I2.w, in1, B2.w));
            step1(pre, H2, c2, h2v);
            out[(size_t)b * T_ + (tt - 2)] = h2v;
        }
        p0 = p1; p1 = pn;
    }
}

// ---------------------------------------------------------------------------
extern "C" void kernel_launch(void* const* d_in, const int* in_sizes, int n_in,
                              void* d_out, int out_size)
{
    const float* x = (const float*)d_in[0];
    const float *wih_a0 = (const float*)d_in[1],  *whh_a0 = (const float*)d_in[2];
    const float *bih_a0 = (const float*)d_in[3],  *bhh_a0 = (const float*)d_in[4];
    const float *wih_a1 = (const float*)d_in[5],  *whh_a1 = (const float*)d_in[6];
    const float *bih_a1 = (const float*)d_in[7],  *bhh_a1 = (const float*)d_in[8];
    const float *wih_a2 = (const float*)d_in[9],  *whh_a2 = (const float*)d_in[10];
    const float *bih_a2 = (const float*)d_in[11], *bhh_a2 = (const float*)d_in[12];
    const float *wih_b0 = (const float*)d_in[13], *whh_b0 = (const float*)d_in[14];
    const float *bih_b0 = (const float*)d_in[15], *bhh_b0 = (const float*)d_in[16];
    const float *wih_b1 = (const float*)d_in[17], *whh_b1 = (const float*)d_in[18];
    const float *bih_b1 = (const float*)d_in[19], *bhh_b1 = (const float*)d_in[20];
    const float *wih_b2 = (const float*)d_in[21], *whh_b2 = (const float*)d_in[22];
    const float *bih_b2 = (const float*)d_in[23], *bhh_b2 = (const float*)d_in[24];
    float* out = (float*)d_out;

    cudaFuncSetAttribute(fuseA, cudaFuncAttributeMaxDynamicSharedMemorySize,
                         SMEM_FUSE_BYTES);

    // fused a0+a1+a2 pipeline -> g_seqA
    fuseA<<<NPAIR, 256, SMEM_FUSE_BYTES>>>(
        x,
        wih_a0, whh_a0, bih_a0, bhh_a0,
        wih_a1, whh_a1, bih_a1, bhh_a1,
        wih_a2, whh_a2, bih_a2, bhh_a2);
    // b0 pre-gates from g_seqA
    preb0<<<512, 256>>>(wih_b0, bih_b0, bhh_b0);
    // b0/b1/b2 fused scalar recurrences -> out
    b012<<<8, 32>>>(whh_b0, wih_b1, whh_b1, bih_b1, bhh_b1,
                    wih_b2, whh_b2, bih_b2, bhh_b2, out);
}